// round 3
// baseline (speedup 1.0000x reference)
#include <cuda_runtime.h>
#include <math.h>

typedef unsigned long long ull;

#define BB 128
#define TT 512
#define FF 256
#define HH 128
#define G4 512   // 4*H

// ---- device scratch (no allocation allowed) ----
__device__ float g_xzf[BB * TT * G4];      // input projection, forward dir
__device__ float g_xzb[BB * TT * G4];      // input projection, backward dir
__device__ float g_y0 [BB * TT * 2 * HH];  // layer-0 bidirectional output
__device__ float g_Up0[2 * HH * G4];       // permuted U, layer 0 (f,b)
__device__ float g_Up1[2 * HH * G4];       // permuted U, layer 1 (f,b)

// ---- packed f32x2 helpers (Blackwell) ----
__device__ __forceinline__ ull pk(float lo, float hi) {
    ull r; asm("mov.b64 %0, {%1,%2};" : "=l"(r) : "f"(lo), "f"(hi)); return r;
}
__device__ __forceinline__ float2 upk(ull v) {
    float2 r; asm("mov.b64 {%0,%1}, %2;" : "=f"(r.x), "=f"(r.y) : "l"(v)); return r;
}
__device__ __forceinline__ void fma2(ull& d, ull a, ull b) {
    asm("fma.rn.f32x2 %0, %1, %2, %0;" : "+l"(d) : "l"(a), "l"(b));
}

__device__ __forceinline__ float sigm(float z) {
    return 1.f / (1.f + __expf(-z));
}
__device__ __forceinline__ float ftanh(float x) {
    x = fmaxf(fminf(x, 15.f), -15.f);
    float e = __expf(-2.f * x);
    return (1.f - e) / (1.f + e);
}

// ---------------------------------------------------------------------------
// Permute U: dst[dir][k][j*4+gate] = U_dir[k][gate*128 + j]
// so each hidden unit's 4 gate columns become one contiguous float4.
// ---------------------------------------------------------------------------
__global__ void permU(const float* __restrict__ Uf, const float* __restrict__ Ub,
                      int which)
{
    float* dst = which ? g_Up1 : g_Up0;
    int idx = blockIdx.x * 256 + threadIdx.x;     // [0, 2*128*512)
    if (idx >= 2 * HH * G4) return;
    int dir = idx >> 16;
    int r   = idx & 65535;
    int k   = r >> 9;
    int col = r & 511;
    int j   = col >> 2;
    int gt  = col & 3;
    const float* U = dir ? Ub : Uf;
    dst[idx] = U[k * G4 + gt * HH + j];
}

// ---------------------------------------------------------------------------
// Projection GEMM: C[M=65536, 512] = A[M, 256] @ W[256, 512] + bias
// 128x128 CTA tile, ktile=32, 256 threads, 8x8 microtile, f32x2 FMAs.
// A tile stored duplicated as (a,a) 64-bit pairs so the inner loop needs no
// packing on the A side; B pairs come free from float4 loads.
// ---------------------------------------------------------------------------
__global__ __launch_bounds__(256) void gemm_bias(
    const float* __restrict__ Aext, int useY0,
    const float* __restrict__ W, const float* __restrict__ bias,
    int dstB)
{
    const int K = FF;
    const int N = G4;
    const float* A = useY0 ? g_y0 : Aext;
    float* C = dstB ? g_xzb : g_xzf;

    __shared__ ull   Asd[32][128];   // duplicated A tile, k-major (32 KB)
    __shared__ float Bs [32][128];   // B tile (16 KB)

    const int tid = threadIdx.x;
    const int bm = blockIdx.y * 128;
    const int bn = blockIdx.x * 128;
    const int tx = tid & 15;
    const int ty = tid >> 4;

    ull acc[8][4];
    #pragma unroll
    for (int i = 0; i < 8; i++)
        #pragma unroll
        for (int j = 0; j < 4; j++) acc[i][j] = 0ULL;

    for (int k0 = 0; k0 < K; k0 += 32) {
        // A tile 128x32 -> transposed, duplicated
        #pragma unroll
        for (int i = 0; i < 4; i++) {
            int idx = tid + i * 256;
            int ar = idx >> 3;          // 0..127 (m)
            int ac = (idx & 7) * 4;     // 0..28  (k)
            float4 v = *(const float4*)&A[(size_t)(bm + ar) * K + k0 + ac];
            Asd[ac + 0][ar] = pk(v.x, v.x);
            Asd[ac + 1][ar] = pk(v.y, v.y);
            Asd[ac + 2][ar] = pk(v.z, v.z);
            Asd[ac + 3][ar] = pk(v.w, v.w);
        }
        // B tile 32x128
        #pragma unroll
        for (int i = 0; i < 4; i++) {
            int idx = tid + i * 256;
            int br = idx >> 5;
            int bc = (idx & 31) * 4;
            *(float4*)&Bs[br][bc] = *(const float4*)&W[(size_t)(k0 + br) * N + bn + bc];
        }
        __syncthreads();

        #pragma unroll
        for (int k = 0; k < 32; k++) {
            ulonglong2 a01 = *(ulonglong2*)&Asd[k][ty * 8 + 0];
            ulonglong2 a23 = *(ulonglong2*)&Asd[k][ty * 8 + 2];
            ulonglong2 a45 = *(ulonglong2*)&Asd[k][ty * 8 + 4];
            ulonglong2 a67 = *(ulonglong2*)&Asd[k][ty * 8 + 6];
            ull ad[8] = { a01.x, a01.y, a23.x, a23.y, a45.x, a45.y, a67.x, a67.y };
            float4 bA = *(float4*)&Bs[k][tx * 8];
            float4 bB = *(float4*)&Bs[k][tx * 8 + 4];
            ull bp[4] = { pk(bA.x, bA.y), pk(bA.z, bA.w),
                          pk(bB.x, bB.y), pk(bB.z, bB.w) };
            #pragma unroll
            for (int i = 0; i < 8; i++)
                #pragma unroll
                for (int j = 0; j < 4; j++)
                    fma2(acc[i][j], ad[i], bp[j]);
        }
        __syncthreads();
    }

    float bv[8];
    *(float4*)&bv[0] = *(const float4*)&bias[bn + tx * 8];
    *(float4*)&bv[4] = *(const float4*)&bias[bn + tx * 8 + 4];

    #pragma unroll
    for (int i = 0; i < 8; i++) {
        int row = bm + ty * 8 + i;
        float2 p0 = upk(acc[i][0]);
        float2 p1 = upk(acc[i][1]);
        float2 p2 = upk(acc[i][2]);
        float2 p3 = upk(acc[i][3]);
        float4 o0, o1;
        o0.x = p0.x + bv[0]; o0.y = p0.y + bv[1];
        o0.z = p1.x + bv[2]; o0.w = p1.y + bv[3];
        o1.x = p2.x + bv[4]; o1.y = p2.y + bv[5];
        o1.z = p3.x + bv[6]; o1.w = p3.y + bv[7];
        *(float4*)&C[(size_t)row * N + bn + tx * 8]     = o0;
        *(float4*)&C[(size_t)row * N + bn + tx * 8 + 4] = o1;
    }
}

// ---------------------------------------------------------------------------
// Recurrence: 64 CTAs = (2 dirs) x (32 groups of 4 batch rows). 512 threads.
// Thread (j = tid>>2, kc = tid&3): unit j (4 gate cols), k-chunk kc (32 k).
// U' (gate-interleaved) lives in smem for 24/32 rows of each chunk (192 KB);
// the last 8 rows of each chunk stream from L2 (4 MB/step chip-wide).
// k-chunk partials reduced with shfl.bfly (kc lives in lane bits 0-1).
// h double-buffered in smem as duplicated (h,h) pairs -> pure f32x2 mainloop.
// c state in a register for row b = kc.
// ---------------------------------------------------------------------------
#define KSMEM_PER_CHUNK 24
#define US_ENTRIES (4 * KSMEM_PER_CHUNK * HH)          // 96*128 ulonglong2
#define SMEM_US_BYTES (US_ENTRIES * 16)                // 196608
#define SMEM_REC_TOTAL (SMEM_US_BYTES + 2 * HH * 4 * 8)  // + 8 KB hdup

__global__ __launch_bounds__(512) void lstm_rec(
    int layer, float* __restrict__ final_out, int last_only)
{
    extern __shared__ char sm_[];
    ulonglong2* Us = (ulonglong2*)sm_;                         // [96][128]
    ull (*hdup)[HH][4] = (ull(*)[HH][4])(sm_ + SMEM_US_BYTES); // [2][128][4]

    const int tid   = threadIdx.x;
    const int dir   = blockIdx.x >> 5;
    const int chunk = blockIdx.x & 31;
    const int bg0   = chunk * 4;
    const int j     = tid >> 2;     // hidden unit
    const int kc    = tid & 3;      // k chunk

    const float* xz = dir ? g_xzb : g_xzf;
    const float* Uall = layer ? g_Up1 : g_Up0;
    const float* U = Uall + (size_t)dir * (HH * G4);

    // Park 24 of each chunk's 32 k-rows in smem.
    for (int idx = tid; idx < US_ENTRIES; idx += 512) {
        int ksm = idx >> 7;
        int jj  = idx & 127;
        int kc2 = ksm / KSMEM_PER_CHUNK;
        int kk  = ksm - kc2 * KSMEM_PER_CHUNK;
        int k   = kc2 * 32 + kk;
        Us[idx] = *(const ulonglong2*)(U + (size_t)k * G4 + jj * 4);
    }
    hdup[0][tid >> 2][tid & 3] = 0ULL;
    float c_r = 0.f;
    __syncthreads();

    for (int s = 0; s < TT; s++) {
        const int t = dir ? (TT - 1 - s) : s;
        const int buf = s & 1;

        // acc pairs: A = (i,f), B = (g,o), for batch rows 0..3
        ull accA0 = 0, accA1 = 0, accA2 = 0, accA3 = 0;
        ull accB0 = 0, accB1 = 0, accB2 = 0, accB3 = 0;

        // smem part of this chunk
        #pragma unroll 8
        for (int kk = 0; kk < KSMEM_PER_CHUNK; kk++) {
            ulonglong2 u = Us[(kc * KSMEM_PER_CHUNK + kk) * HH + j];
            int k = kc * 32 + kk;
            ulonglong2 h01 = *(ulonglong2*)&hdup[buf][k][0];
            ulonglong2 h23 = *(ulonglong2*)&hdup[buf][k][2];
            fma2(accA0, h01.x, u.x); fma2(accB0, h01.x, u.y);
            fma2(accA1, h01.y, u.x); fma2(accB1, h01.y, u.y);
            fma2(accA2, h23.x, u.x); fma2(accB2, h23.x, u.y);
            fma2(accA3, h23.y, u.x); fma2(accB3, h23.y, u.y);
        }
        // streamed part (rows 24..31 of this chunk, L2-resident)
        #pragma unroll
        for (int kk = KSMEM_PER_CHUNK; kk < 32; kk++) {
            int k = kc * 32 + kk;
            ulonglong2 u = *(const ulonglong2*)(U + (size_t)k * G4 + j * 4);
            ulonglong2 h01 = *(ulonglong2*)&hdup[buf][k][0];
            ulonglong2 h23 = *(ulonglong2*)&hdup[buf][k][2];
            fma2(accA0, h01.x, u.x); fma2(accB0, h01.x, u.y);
            fma2(accA1, h01.y, u.x); fma2(accB1, h01.y, u.y);
            fma2(accA2, h23.x, u.x); fma2(accB2, h23.x, u.y);
            fma2(accA3, h23.y, u.x); fma2(accB3, h23.y, u.y);
        }

        // unpack to 16 floats: v[0..3]=i, v[4..7]=f, v[8..11]=g, v[12..15]=o
        float v[16];
        {
            float2 p;
            p = upk(accA0); v[0] = p.x; v[4] = p.y;
            p = upk(accA1); v[1] = p.x; v[5] = p.y;
            p = upk(accA2); v[2] = p.x; v[6] = p.y;
            p = upk(accA3); v[3] = p.x; v[7] = p.y;
            p = upk(accB0); v[8] = p.x; v[12] = p.y;
            p = upk(accB1); v[9] = p.x; v[13] = p.y;
            p = upk(accB2); v[10] = p.x; v[14] = p.y;
            p = upk(accB3); v[11] = p.x; v[15] = p.y;
        }
        // reduce over kc (lane bits 0-1)
        #pragma unroll
        for (int m = 1; m <= 2; m <<= 1) {
            #pragma unroll
            for (int q = 0; q < 16; q++)
                v[q] += __shfl_xor_sync(0xffffffffu, v[q], m);
        }

        // gate phase: this thread owns row b = kc, unit j
        const int b = kc;
        const float* zrow = xz + ((size_t)(bg0 + b) * TT + t) * G4;
        float zi = v[b]      + zrow[j];
        float zf = v[4 + b]  + zrow[HH + j];
        float zg = v[8 + b]  + zrow[2 * HH + j];
        float zo = v[12 + b] + zrow[3 * HH + j];

        float ig = sigm(zi);
        float fg = sigm(zf);
        float gg = ftanh(zg);
        float og = sigm(zo);
        c_r = fg * c_r + ig * gg;
        float h = og * ftanh(c_r);

        hdup[buf ^ 1][j][kc] = pk(h, h);

        if (!last_only) {
            g_y0[((size_t)(bg0 + b) * TT + t) * (2 * HH) + dir * HH + j] = h;
        } else if (s == TT - 1) {
            final_out[(size_t)(bg0 + b) * (2 * HH) + dir * HH + j] = h;
        }
        __syncthreads();
    }
}

// ---------------------------------------------------------------------------
extern "C" void kernel_launch(void* const* d_in, const int* in_sizes, int n_in,
                              void* d_out, int out_size)
{
    (void)in_sizes; (void)n_in; (void)out_size;
    const float* x   = (const float*)d_in[0];
    const float* W0f = (const float*)d_in[1];
    const float* U0f = (const float*)d_in[2];
    const float* b0f = (const float*)d_in[3];
    const float* W0b = (const float*)d_in[4];
    const float* U0b = (const float*)d_in[5];
    const float* b0b = (const float*)d_in[6];
    const float* W1f = (const float*)d_in[7];
    const float* U1f = (const float*)d_in[8];
    const float* b1f = (const float*)d_in[9];
    const float* W1b = (const float*)d_in[10];
    const float* U1b = (const float*)d_in[11];
    const float* b1b = (const float*)d_in[12];
    float* out = (float*)d_out;

    cudaFuncSetAttribute(lstm_rec,
        cudaFuncAttributeMaxDynamicSharedMemorySize, SMEM_REC_TOTAL);

    dim3 gg(4, 512);   // N blocks x M blocks (M = B*T = 65536)

    // Layer 0
    permU<<<512, 256>>>(U0f, U0b, 0);
    gemm_bias<<<gg, 256>>>(x, 0, W0f, b0f, 0);
    gemm_bias<<<gg, 256>>>(x, 0, W0b, b0b, 1);
    lstm_rec<<<64, 512, SMEM_REC_TOTAL>>>(0, nullptr, 0);

    // Layer 1 (input = g_y0)
    permU<<<512, 256>>>(U1f, U1b, 1);
    gemm_bias<<<gg, 256>>>(nullptr, 1, W1f, b1f, 0);
    gemm_bias<<<gg, 256>>>(nullptr, 1, W1b, b1b, 1);
    lstm_rec<<<64, 512, SMEM_REC_TOTAL>>>(1, out, 1);
}

// round 5
// speedup vs baseline: 4.4202x; 4.4202x over previous
#include <cuda_runtime.h>
#include <math.h>

typedef unsigned long long ull;

#define BB 128
#define TT 512
#define FF 256
#define HH 128
#define G4 512   // 4*H

// ---- device scratch (no allocation allowed) ----
__device__ float g_xzf[BB * TT * G4];       // input projection, forward dir
__device__ float g_xzb[BB * TT * G4];       // input projection, backward dir
__device__ float g_y0 [BB * TT * 2 * HH];   // layer-0 bidirectional output
__device__ float g_Up0[2 * 4 * HH * HH];    // permuted U layer0: [dir][g][j][k]
__device__ float g_Up1[2 * 4 * HH * HH];    // permuted U layer1

// ---- packed f32x2 helpers (Blackwell) ----
__device__ __forceinline__ float2 upk(ull v) {
    float2 r; asm("mov.b64 {%0,%1}, %2;" : "=f"(r.x), "=f"(r.y) : "l"(v)); return r;
}
__device__ __forceinline__ void fma2(ull& d, ull a, ull b) {
    asm("fma.rn.f32x2 %0, %1, %2, %0;" : "+l"(d) : "l"(a), "l"(b));
}
__device__ __forceinline__ float sigm(float z) {
    return 1.f / (1.f + __expf(-z));
}
__device__ __forceinline__ float ftanh(float x) {
    x = fmaxf(fminf(x, 15.f), -15.f);
    float e = __expf(-2.f * x);
    return (1.f - e) / (1.f + e);
}

// ---------------------------------------------------------------------------
// Permute U: dst[dir][g][j][k] = U_dir[k][g*128 + j]   (k-minor for LDS.64 pairs)
// ---------------------------------------------------------------------------
__global__ void permU(const float* __restrict__ Uf, const float* __restrict__ Ub,
                      int which)
{
    float* dst = which ? g_Up1 : g_Up0;
    int idx = blockIdx.x * 256 + threadIdx.x;   // [0, 131072)
    if (idx >= 2 * 4 * HH * HH) return;
    int dir = idx >> 16;
    int col = (idx >> 7) & 511;   // g*128 + j
    int k   = idx & 127;
    int g   = col >> 7;
    int j   = col & 127;
    const float* U = dir ? Ub : Uf;
    dst[idx] = U[k * G4 + g * HH + j];
}

// ---------------------------------------------------------------------------
// Projection GEMM: C[65536, 512] = A[65536, 256] @ W[256, 512] + bias
// k-paired f32x2: acc lo/hi hold even/odd-k partial sums (no dup, no packing).
// CTA tile 128m x 64n, 256 threads, 8m x 4n microtile, double-buffered smem.
//   As[buf][m(128)][k(32)]  - m-major = global layout, conflict-free STS.128
//   Bs[buf][n(64)][k(34)]   - transposed, row pad 34 -> conflict-free LDS.64
// ---------------------------------------------------------------------------
#define GEMM_SMEM_F (2 * 128 * 32 + 2 * 64 * 34)     // 12544 floats
#define GEMM_SMEM_B (GEMM_SMEM_F * 4)                // 50176 bytes

__global__ __launch_bounds__(256, 2) void gemm_bias(
    const float* __restrict__ Aext, int useY0,
    const float* __restrict__ W, const float* __restrict__ bias,
    int dstB)
{
    extern __shared__ __align__(16) float gsm[];
    float (*As)[128][32] = (float(*)[128][32])gsm;
    float (*Bs)[64][34]  = (float(*)[64][34])(gsm + 2 * 128 * 32);

    const float* A = useY0 ? g_y0 : Aext;
    float* C = dstB ? g_xzb : g_xzf;

    const int tid = threadIdx.x;
    const int tx = tid & 15;      // n-group
    const int ty = tid >> 4;      // m-group
    const int bm = blockIdx.y * 128;
    const int bn = blockIdx.x * 64;

    ull acc[8][4];
    #pragma unroll
    for (int i = 0; i < 8; i++)
        #pragma unroll
        for (int j = 0; j < 4; j++) acc[i][j] = 0ULL;

    float4 ar[4], br[2];

    // stage global -> regs (ktile 0)
    {
        #pragma unroll
        for (int ii = 0; ii < 4; ii++) {
            int idx = tid + ii * 256;
            ar[ii] = *(const float4*)&A[(size_t)(bm + (idx >> 3)) * FF + (idx & 7) * 4];
        }
        #pragma unroll
        for (int ii = 0; ii < 2; ii++) {
            int idx = tid + ii * 256;
            br[ii] = *(const float4*)&W[(size_t)(idx >> 4) * G4 + bn + (idx & 15) * 4];
        }
    }
    // regs -> smem buf 0
    #pragma unroll
    for (int ii = 0; ii < 4; ii++) {
        int idx = tid + ii * 256;
        *(float4*)&As[0][idx >> 3][(idx & 7) * 4] = ar[ii];
    }
    #pragma unroll
    for (int ii = 0; ii < 2; ii++) {
        int idx = tid + ii * 256;
        int kr = idx >> 4, nc = (idx & 15) * 4;
        Bs[0][nc + 0][kr] = br[ii].x;
        Bs[0][nc + 1][kr] = br[ii].y;
        Bs[0][nc + 2][kr] = br[ii].z;
        Bs[0][nc + 3][kr] = br[ii].w;
    }
    __syncthreads();

    int stage = 0;
    for (int kt = 0; kt < 8; kt++) {
        if (kt < 7) {
            const int k0 = (kt + 1) * 32;
            #pragma unroll
            for (int ii = 0; ii < 4; ii++) {
                int idx = tid + ii * 256;
                ar[ii] = *(const float4*)&A[(size_t)(bm + (idx >> 3)) * FF + k0 + (idx & 7) * 4];
            }
            #pragma unroll
            for (int ii = 0; ii < 2; ii++) {
                int idx = tid + ii * 256;
                br[ii] = *(const float4*)&W[(size_t)(k0 + (idx >> 4)) * G4 + bn + (idx & 15) * 4];
            }
        }

        #pragma unroll
        for (int kp = 0; kp < 16; kp++) {
            ull av[8], bv[4];
            #pragma unroll
            for (int i = 0; i < 8; i++)
                av[i] = *(const ull*)&As[stage][ty * 8 + i][kp * 2];
            #pragma unroll
            for (int j = 0; j < 4; j++)
                bv[j] = *(const ull*)&Bs[stage][tx + 16 * j][kp * 2];
            #pragma unroll
            for (int i = 0; i < 8; i++)
                #pragma unroll
                for (int j = 0; j < 4; j++)
                    fma2(acc[i][j], av[i], bv[j]);
        }

        if (kt < 7) {
            const int st = stage ^ 1;
            #pragma unroll
            for (int ii = 0; ii < 4; ii++) {
                int idx = tid + ii * 256;
                *(float4*)&As[st][idx >> 3][(idx & 7) * 4] = ar[ii];
            }
            #pragma unroll
            for (int ii = 0; ii < 2; ii++) {
                int idx = tid + ii * 256;
                int kr = idx >> 4, nc = (idx & 15) * 4;
                Bs[st][nc + 0][kr] = br[ii].x;
                Bs[st][nc + 1][kr] = br[ii].y;
                Bs[st][nc + 2][kr] = br[ii].z;
                Bs[st][nc + 3][kr] = br[ii].w;
            }
        }
        __syncthreads();
        stage ^= 1;
    }

    float bvx[4];
    #pragma unroll
    for (int j = 0; j < 4; j++) bvx[j] = bias[bn + tx + 16 * j];

    #pragma unroll
    for (int i = 0; i < 8; i++) {
        size_t row = (size_t)(bm + ty * 8 + i) * G4 + bn + tx;
        #pragma unroll
        for (int j = 0; j < 4; j++) {
            float2 p = upk(acc[i][j]);
            C[row + 16 * j] = p.x + p.y + bvx[j];
        }
    }
}

// ---------------------------------------------------------------------------
// Recurrence: 128 CTAs = (2 dirs) x (64 groups of 2 batch rows), 512 threads.
// Thread: kc = tid>>7 (k-chunk of 32, per warp-group), j = tid&127 (unit).
// U layout: Usm[g*128+j][col of 98] holds the first 24 k of each chunk
//   (conflict-free: lane stride 392B -> banks 2j). Last 8 k/chunk live in
//   registers (loaded once). h read as broadcast ulonglong2 pairs.
// kc-reduction via small padded smem buffer zp. Owners (kc<2) do gates for
// batch row b=kc; c state in a register.
// ---------------------------------------------------------------------------
#define USM_COLPAD 98
#define USM_FLOATS (512 * USM_COLPAD)                // 50176 floats
#define SM_ZP_OFF  USM_FLOATS                        // zp: [4][2][128] float4 = 4096 floats
#define SM_HB_OFF  (USM_FLOATS + 4096)               // hb: [2][2][128] = 512 floats
#define REC_SMEM_B ((USM_FLOATS + 4096 + 512) * 4)   // 219136 bytes

__global__ __launch_bounds__(512, 1) void lstm_rec(
    int layer, float* __restrict__ final_out, int last_only)
{
    extern __shared__ __align__(16) float sm[];
    float*  Usm = sm;
    float4* zp  = (float4*)(sm + SM_ZP_OFF);   // [(kc*2+b)*128 + j]
    float*  hb  = sm + SM_HB_OFF;              // [(buf*2+b)*128 + j]

    const int tid = threadIdx.x;
    const int kc  = tid >> 7;     // 0..3
    const int j   = tid & 127;
    const int dir   = blockIdx.x >> 6;
    const int chunk = blockIdx.x & 63;
    const int bg0   = chunk * 2;

    const float* xz = dir ? g_xzb : g_xzf;
    const float* Up = (layer ? g_Up1 : g_Up0) + dir * 65536;

    // preload parked U (first 24 k of each chunk) into smem
    for (int idx = tid; idx < 512 * 96; idx += 512) {
        int col = idx / 96;
        int p   = idx - col * 96;
        int cc  = p / 24;
        int gk  = cc * 32 + (p - cc * 24);
        Usm[col * USM_COLPAD + p] = Up[col * 128 + gk];
    }
    // register-resident U: last 8 k of this thread's chunk, 4 gates
    ull ureg[4][4];
    #pragma unroll
    for (int g = 0; g < 4; g++)
        #pragma unroll
        for (int q = 0; q < 4; q++)
            ureg[g][q] = *(const ull*)&Up[(g * 128 + j) * 128 + kc * 32 + 24 + 2 * q];

    if (tid < 256) hb[tid] = 0.f;   // hb buf 0
    float c_r = 0.f;
    __syncthreads();

    for (int s = 0; s < TT; s++) {
        const int t = dir ? (TT - 1 - s) : s;
        const int buf = s & 1;

        // prefetch xz (owners only; independent of h)
        float xzg0 = 0.f, xzg1 = 0.f, xzg2 = 0.f, xzg3 = 0.f;
        if (kc < 2) {
            const float* zr = xz + ((size_t)(bg0 + kc) * TT + t) * G4 + j;
            xzg0 = zr[0]; xzg1 = zr[HH]; xzg2 = zr[2 * HH]; xzg3 = zr[3 * HH];
        }

        ull acc[4][2];
        #pragma unroll
        for (int g = 0; g < 4; g++) { acc[g][0] = 0ULL; acc[g][1] = 0ULL; }

        const float* hbB = hb + buf * 256;

        // parked part: 24 k = 6 quads
        #pragma unroll
        for (int qq = 0; qq < 6; qq++) {
            const int k4 = kc * 32 + qq * 4;
            const int p  = kc * 24 + qq * 4;
            ulonglong2 ha = *(const ulonglong2*)&hbB[k4];        // b=0
            ulonglong2 hc = *(const ulonglong2*)&hbB[128 + k4];  // b=1
            #pragma unroll
            for (int g = 0; g < 4; g++) {
                const float* uc = &Usm[(g * 128 + j) * USM_COLPAD + p];
                ull ua = *(const ull*)uc;
                ull ub = *(const ull*)(uc + 2);
                fma2(acc[g][0], ha.x, ua); fma2(acc[g][0], ha.y, ub);
                fma2(acc[g][1], hc.x, ua); fma2(acc[g][1], hc.y, ub);
            }
        }
        // register part: last 8 k = 2 quads
        #pragma unroll
        for (int qq = 0; qq < 2; qq++) {
            const int k4 = kc * 32 + 24 + qq * 4;
            ulonglong2 ha = *(const ulonglong2*)&hbB[k4];
            ulonglong2 hc = *(const ulonglong2*)&hbB[128 + k4];
            #pragma unroll
            for (int g = 0; g < 4; g++) {
                fma2(acc[g][0], ha.x, ureg[g][2 * qq]); fma2(acc[g][0], ha.y, ureg[g][2 * qq + 1]);
                fma2(acc[g][1], hc.x, ureg[g][2 * qq]); fma2(acc[g][1], hc.y, ureg[g][2 * qq + 1]);
            }
        }

        // fold halves
        float v[4][2];
        #pragma unroll
        for (int g = 0; g < 4; g++) {
            float2 p0 = upk(acc[g][0]); v[g][0] = p0.x + p0.y;
            float2 p1 = upk(acc[g][1]); v[g][1] = p1.x + p1.y;
        }

        // publish partials for rows this thread doesn't own
        if (kc < 2) {
            const int bw = 1 - kc;
            zp[(kc * 2 + bw) * 128 + j] = make_float4(v[0][bw], v[1][bw], v[2][bw], v[3][bw]);
        } else {
            zp[(kc * 2 + 0) * 128 + j] = make_float4(v[0][0], v[1][0], v[2][0], v[3][0]);
            zp[(kc * 2 + 1) * 128 + j] = make_float4(v[0][1], v[1][1], v[2][1], v[3][1]);
        }
        __syncthreads();

        if (kc < 2) {
            const int b = kc;
            float z0 = v[0][b] + xzg0;
            float z1 = v[1][b] + xzg1;
            float z2 = v[2][b] + xzg2;
            float z3 = v[3][b] + xzg3;
            #pragma unroll
            for (int kc2 = 0; kc2 < 4; kc2++) {
                if (kc2 == b) continue;
                float4 q = zp[(kc2 * 2 + b) * 128 + j];
                z0 += q.x; z1 += q.y; z2 += q.z; z3 += q.w;
            }
            float ig = sigm(z0);
            float fg = sigm(z1);
            float gg = ftanh(z2);
            float og = sigm(z3);
            c_r = fg * c_r + ig * gg;
            float h = og * ftanh(c_r);

            hb[(buf ^ 1) * 256 + b * 128 + j] = h;

            if (!last_only) {
                g_y0[((size_t)(bg0 + b) * TT + t) * (2 * HH) + dir * HH + j] = h;
            } else if (s == TT - 1) {
                final_out[(size_t)(bg0 + b) * (2 * HH) + dir * HH + j] = h;
            }
        }
        __syncthreads();
    }
}

// ---------------------------------------------------------------------------
extern "C" void kernel_launch(void* const* d_in, const int* in_sizes, int n_in,
                              void* d_out, int out_size)
{
    (void)in_sizes; (void)n_in; (void)out_size;
    const float* x   = (const float*)d_in[0];
    const float* W0f = (const float*)d_in[1];
    const float* U0f = (const float*)d_in[2];
    const float* b0f = (const float*)d_in[3];
    const float* W0b = (const float*)d_in[4];
    const float* U0b = (const float*)d_in[5];
    const float* b0b = (const float*)d_in[6];
    const float* W1f = (const float*)d_in[7];
    const float* U1f = (const float*)d_in[8];
    const float* b1f = (const float*)d_in[9];
    const float* W1b = (const float*)d_in[10];
    const float* U1b = (const float*)d_in[11];
    const float* b1b = (const float*)d_in[12];
    float* out = (float*)d_out;

    cudaFuncSetAttribute(gemm_bias,
        cudaFuncAttributeMaxDynamicSharedMemorySize, GEMM_SMEM_B);
    cudaFuncSetAttribute(lstm_rec,
        cudaFuncAttributeMaxDynamicSharedMemorySize, REC_SMEM_B);

    dim3 gg(8, 512);   // 512/64 n-tiles x 65536/128 m-tiles

    // Layer 0
    permU<<<512, 256>>>(U0f, U0b, 0);
    gemm_bias<<<gg, 256, GEMM_SMEM_B>>>(x, 0, W0f, b0f, 0);
    gemm_bias<<<gg, 256, GEMM_SMEM_B>>>(x, 0, W0b, b0b, 1);
    lstm_rec<<<128, 512, REC_SMEM_B>>>(0, nullptr, 0);

    // Layer 1 (input = g_y0)
    permU<<<512, 256>>>(U1f, U1b, 1);
    gemm_bias<<<gg, 256, GEMM_SMEM_B>>>(nullptr, 1, W1f, b1f, 0);
    gemm_bias<<<gg, 256, GEMM_SMEM_B>>>(nullptr, 1, W1b, b1b, 1);
    lstm_rec<<<128, 512, REC_SMEM_B>>>(1, out, 1);
}

// round 8
// speedup vs baseline: 4.6509x; 1.0522x over previous
#include <cuda_runtime.h>
#include <math.h>

typedef unsigned long long ull;

#define BB 128
#define TT 512
#define FF 256
#define HH 128
#define G4 512   // 4*H

// ---- device scratch (no allocation allowed) ----
__device__ float g_xzf[BB * TT * G4];       // input projection, forward dir
__device__ float g_xzb[BB * TT * G4];       // input projection, backward dir
__device__ float g_y0 [BB * TT * 2 * HH];   // layer-0 bidirectional output
__device__ float g_Up0[2 * 4 * HH * HH];    // permuted U layer0: [dir][g][j][k]
__device__ float g_Up1[2 * 4 * HH * HH];    // permuted U layer1

// ---- packed f32x2 helpers (Blackwell) ----
__device__ __forceinline__ float2 upk(ull v) {
    float2 r; asm("mov.b64 {%0,%1}, %2;" : "=f"(r.x), "=f"(r.y) : "l"(v)); return r;
}
__device__ __forceinline__ void fma2(ull& d, ull a, ull b) {
    asm("fma.rn.f32x2 %0, %1, %2, %0;" : "+l"(d) : "l"(a), "l"(b));
}

// ---- FFMA-only transcendentals (zero MUFU: MUFU rt=8/SMSP was the R5 gate
//      bottleneck at ~2560 MUFU/step/CTA). ----
// e^x for x in [-31, 31]; rel err ~2.4e-6.
__device__ __forceinline__ float fexp(float x) {
    const float L2E = 1.442695041f;
    float t = fmaf(x, L2E, 12582912.0f);       // magic round-to-nearest
    int  ti = __float_as_int(t);
    float n = t - 12582912.0f;                 // n = round(x*log2e)
    float f = fmaf(x, L2E, -n);                // f in [-0.5, 0.5]
    float p =          1.3335591e-3f;          // 2^f Taylor (deg 5)
    p = fmaf(p, f, 9.6181291e-3f);
    p = fmaf(p, f, 5.5504109e-2f);
    p = fmaf(p, f, 2.4022651e-1f);
    p = fmaf(p, f, 6.9314718e-1f);
    p = fmaf(p, f, 1.0f);
    int e = ((ti & 0x7FFFFF) - 0x400000) << 23;  // n as exponent bits
    return __int_as_float(__float_as_int(p) + e);
}
// 1/d for normal positive d; bit-trick seed + 3 Newton; rel err ~5e-11.
__device__ __forceinline__ float frcp(float d) {
    float r = __int_as_float(0x7EF477D5 - __float_as_int(d));
    r = r * fmaf(-d, r, 2.0f);
    r = r * fmaf(-d, r, 2.0f);
    r = r * fmaf(-d, r, 2.0f);
    return r;
}
__device__ __forceinline__ float sigm(float z) {
    z = fmaxf(fminf(z, 30.f), -30.f);
    return frcp(1.0f + fexp(-z));
}
__device__ __forceinline__ float ftanh(float x) {
    x = fmaxf(fminf(x, 15.f), -15.f);
    float e = fexp(-2.0f * x);
    return (1.0f - e) * frcp(1.0f + e);
}

// ---------------------------------------------------------------------------
// Permute U: dst[dir][g][j][k] = U_dir[k][g*128 + j]   (k-minor for LDS.64 pairs)
// ---------------------------------------------------------------------------
__global__ void permU(const float* __restrict__ Uf, const float* __restrict__ Ub,
                      int which)
{
    float* dst = which ? g_Up1 : g_Up0;
    int idx = blockIdx.x * 256 + threadIdx.x;   // [0, 131072)
    if (idx >= 2 * 4 * HH * HH) return;
    int dir = idx >> 16;
    int col = (idx >> 7) & 511;   // g*128 + j
    int k   = idx & 127;
    int g   = col >> 7;
    int j   = col & 127;
    const float* U = dir ? Ub : Uf;
    dst[idx] = U[k * G4 + g * HH + j];
}

// ---------------------------------------------------------------------------
// Projection GEMM: C[65536, 512] = A[65536, 256] @ W[256, 512] + bias
// k-paired f32x2: acc lo/hi hold even/odd-k partial sums (no dup, no packing).
// CTA tile 128m x 64n, 256 threads, 8m x 4n microtile, double-buffered smem.
//   As[buf][m(128)][k(32)]  - m-major = global layout, conflict-free STS.128
//   Bs[buf][n(64)][k(34)]   - transposed, row pad 34 -> conflict-free LDS.64
// ---------------------------------------------------------------------------
#define GEMM_SMEM_F (2 * 128 * 32 + 2 * 64 * 34)     // 12544 floats
#define GEMM_SMEM_B (GEMM_SMEM_F * 4)                // 50176 bytes

__global__ __launch_bounds__(256, 2) void gemm_bias(
    const float* __restrict__ Aext, int useY0,
    const float* __restrict__ W, const float* __restrict__ bias,
    int dstB)
{
    extern __shared__ __align__(16) float gsm[];
    float (*As)[128][32] = (float(*)[128][32])gsm;
    float (*Bs)[64][34]  = (float(*)[64][34])(gsm + 2 * 128 * 32);

    const float* A = useY0 ? g_y0 : Aext;
    float* C = dstB ? g_xzb : g_xzf;

    const int tid = threadIdx.x;
    const int tx = tid & 15;      // n-group
    const int ty = tid >> 4;      // m-group
    const int bm = blockIdx.y * 128;
    const int bn = blockIdx.x * 64;

    ull acc[8][4];
    #pragma unroll
    for (int i = 0; i < 8; i++)
        #pragma unroll
        for (int j = 0; j < 4; j++) acc[i][j] = 0ULL;

    float4 ar[4], br[2];

    // stage global -> regs (ktile 0)
    {
        #pragma unroll
        for (int ii = 0; ii < 4; ii++) {
            int idx = tid + ii * 256;
            ar[ii] = *(const float4*)&A[(size_t)(bm + (idx >> 3)) * FF + (idx & 7) * 4];
        }
        #pragma unroll
        for (int ii = 0; ii < 2; ii++) {
            int idx = tid + ii * 256;
            br[ii] = *(const float4*)&W[(size_t)(idx >> 4) * G4 + bn + (idx & 15) * 4];
        }
    }
    // regs -> smem buf 0
    #pragma unroll
    for (int ii = 0; ii < 4; ii++) {
        int idx = tid + ii * 256;
        *(float4*)&As[0][idx >> 3][(idx & 7) * 4] = ar[ii];
    }
    #pragma unroll
    for (int ii = 0; ii < 2; ii++) {
        int idx = tid + ii * 256;
        int kr = idx >> 4, nc = (idx & 15) * 4;
        Bs[0][nc + 0][kr] = br[ii].x;
        Bs[0][nc + 1][kr] = br[ii].y;
        Bs[0][nc + 2][kr] = br[ii].z;
        Bs[0][nc + 3][kr] = br[ii].w;
    }
    __syncthreads();

    int stage = 0;
    for (int kt = 0; kt < 8; kt++) {
        if (kt < 7) {
            const int k0 = (kt + 1) * 32;
            #pragma unroll
            for (int ii = 0; ii < 4; ii++) {
                int idx = tid + ii * 256;
                ar[ii] = *(const float4*)&A[(size_t)(bm + (idx >> 3)) * FF + k0 + (idx & 7) * 4];
            }
            #pragma unroll
            for (int ii = 0; ii < 2; ii++) {
                int idx = tid + ii * 256;
                br[ii] = *(const float4*)&W[(size_t)(k0 + (idx >> 4)) * G4 + bn + (idx & 15) * 4];
            }
        }

        #pragma unroll
        for (int kp = 0; kp < 16; kp++) {
            ull av[8], bv[4];
            #pragma unroll
            for (int i = 0; i < 8; i++)
                av[i] = *(const ull*)&As[stage][ty * 8 + i][kp * 2];
            #pragma unroll
            for (int j = 0; j < 4; j++)
                bv[j] = *(const ull*)&Bs[stage][tx + 16 * j][kp * 2];
            #pragma unroll
            for (int i = 0; i < 8; i++)
                #pragma unroll
                for (int j = 0; j < 4; j++)
                    fma2(acc[i][j], av[i], bv[j]);
        }

        if (kt < 7) {
            const int st = stage ^ 1;
            #pragma unroll
            for (int ii = 0; ii < 4; ii++) {
                int idx = tid + ii * 256;
                *(float4*)&As[st][idx >> 3][(idx & 7) * 4] = ar[ii];
            }
            #pragma unroll
            for (int ii = 0; ii < 2; ii++) {
                int idx = tid + ii * 256;
                int kr = idx >> 4, nc = (idx & 15) * 4;
                Bs[st][nc + 0][kr] = br[ii].x;
                Bs[st][nc + 1][kr] = br[ii].y;
                Bs[st][nc + 2][kr] = br[ii].z;
                Bs[st][nc + 3][kr] = br[ii].w;
            }
        }
        __syncthreads();
        stage ^= 1;
    }

    float bvx[4];
    #pragma unroll
    for (int j = 0; j < 4; j++) bvx[j] = bias[bn + tx + 16 * j];

    #pragma unroll
    for (int i = 0; i < 8; i++) {
        size_t row = (size_t)(bm + ty * 8 + i) * G4 + bn + tx;
        #pragma unroll
        for (int j = 0; j < 4; j++) {
            float2 p = upk(acc[i][j]);
            C[row + 16 * j] = p.x + p.y + bvx[j];
        }
    }
}

// ---------------------------------------------------------------------------
// Recurrence: 128 CTAs = (2 dirs) x (64 groups of 2 batch rows), 512 threads.
// Thread: kc = tid>>7 (k-chunk of 32, per warp-group), j = tid&127 (unit).
// U layout: Usm[g*128+j][col of 98] holds the first 24 k of each chunk
//   (conflict-free: lane stride 392B -> banks 2j). Last 8 k/chunk live in
//   registers (loaded once). h read as broadcast ulonglong2 pairs.
// kc-reduction via small padded smem buffer zp. Owners (kc<2) do gates for
// batch row b=kc; c state in a register. Gates are FFMA-only (no MUFU).
// ---------------------------------------------------------------------------
#define USM_COLPAD 98
#define USM_FLOATS (512 * USM_COLPAD)                // 50176 floats
#define SM_ZP_OFF  USM_FLOATS                        // zp: [4][2][128] float4 = 4096 floats
#define SM_HB_OFF  (USM_FLOATS + 4096)               // hb: [2][2][128] = 512 floats
#define REC_SMEM_B ((USM_FLOATS + 4096 + 512) * 4)   // 219136 bytes

__global__ __launch_bounds__(512, 1) void lstm_rec(
    int layer, float* __restrict__ final_out, int last_only)
{
    extern __shared__ __align__(16) float sm[];
    float*  Usm = sm;
    float4* zp  = (float4*)(sm + SM_ZP_OFF);   // [(kc*2+b)*128 + j]
    float*  hb  = sm + SM_HB_OFF;              // [(buf*2+b)*128 + j]

    const int tid = threadIdx.x;
    const int kc  = tid >> 7;     // 0..3
    const int j   = tid & 127;
    const int dir   = blockIdx.x >> 6;
    const int chunk = blockIdx.x & 63;
    const int bg0   = chunk * 2;

    const float* xz = dir ? g_xzb : g_xzf;
    const float* Up = (layer ? g_Up1 : g_Up0) + dir * 65536;

    // preload parked U (first 24 k of each chunk) into smem
    for (int idx = tid; idx < 512 * 96; idx += 512) {
        int col = idx / 96;
        int p   = idx - col * 96;
        int cc  = p / 24;
        int gk  = cc * 32 + (p - cc * 24);
        Usm[col * USM_COLPAD + p] = Up[col * 128 + gk];
    }
    // register-resident U: last 8 k of this thread's chunk, 4 gates
    ull ureg[4][4];
    #pragma unroll
    for (int g = 0; g < 4; g++)
        #pragma unroll
        for (int q = 0; q < 4; q++)
            ureg[g][q] = *(const ull*)&Up[(g * 128 + j) * 128 + kc * 32 + 24 + 2 * q];

    if (tid < 256) hb[tid] = 0.f;   // hb buf 0
    float c_r = 0.f;
    __syncthreads();

    for (int s = 0; s < TT; s++) {
        const int t = dir ? (TT - 1 - s) : s;
        const int buf = s & 1;

        // prefetch xz (owners only; independent of h)
        float xzg0 = 0.f, xzg1 = 0.f, xzg2 = 0.f, xzg3 = 0.f;
        if (kc < 2) {
            const float* zr = xz + ((size_t)(bg0 + kc) * TT + t) * G4 + j;
            xzg0 = zr[0]; xzg1 = zr[HH]; xzg2 = zr[2 * HH]; xzg3 = zr[3 * HH];
        }

        ull acc[4][2];
        #pragma unroll
        for (int g = 0; g < 4; g++) { acc[g][0] = 0ULL; acc[g][1] = 0ULL; }

        const float* hbB = hb + buf * 256;

        // parked part: 24 k = 6 quads
        #pragma unroll
        for (int qq = 0; qq < 6; qq++) {
            const int k4 = kc * 32 + qq * 4;
            const int p  = kc * 24 + qq * 4;
            ulonglong2 ha = *(const ulonglong2*)&hbB[k4];        // b=0
            ulonglong2 hc = *(const ulonglong2*)&hbB[128 + k4];  // b=1
            #pragma unroll
            for (int g = 0; g < 4; g++) {
                const float* uc = &Usm[(g * 128 + j) * USM_COLPAD + p];
                ull ua = *(const ull*)uc;
                ull ub = *(const ull*)(uc + 2);
                fma2(acc[g][0], ha.x, ua); fma2(acc[g][0], ha.y, ub);
                fma2(acc[g][1], hc.x, ua); fma2(acc[g][1], hc.y, ub);
            }
        }
        // register part: last 8 k = 2 quads
        #pragma unroll
        for (int qq = 0; qq < 2; qq++) {
            const int k4 = kc * 32 + 24 + qq * 4;
            ulonglong2 ha = *(const ulonglong2*)&hbB[k4];
            ulonglong2 hc = *(const ulonglong2*)&hbB[128 + k4];
            #pragma unroll
            for (int g = 0; g < 4; g++) {
                fma2(acc[g][0], ha.x, ureg[g][2 * qq]); fma2(acc[g][0], ha.y, ureg[g][2 * qq + 1]);
                fma2(acc[g][1], hc.x, ureg[g][2 * qq]); fma2(acc[g][1], hc.y, ureg[g][2 * qq + 1]);
            }
        }

        // fold halves
        float v[4][2];
        #pragma unroll
        for (int g = 0; g < 4; g++) {
            float2 p0 = upk(acc[g][0]); v[g][0] = p0.x + p0.y;
            float2 p1 = upk(acc[g][1]); v[g][1] = p1.x + p1.y;
        }

        // publish partials for rows this thread doesn't own
        if (kc < 2) {
            const int bw = 1 - kc;
            zp[(kc * 2 + bw) * 128 + j] = make_float4(v[0][bw], v[1][bw], v[2][bw], v[3][bw]);
        } else {
            zp[(kc * 2 + 0) * 128 + j] = make_float4(v[0][0], v[1][0], v[2][0], v[3][0]);
            zp[(kc * 2 + 1) * 128 + j] = make_float4(v[0][1], v[1][1], v[2][1], v[3][1]);
        }
        __syncthreads();

        if (kc < 2) {
            const int b = kc;
            float z0 = v[0][b] + xzg0;
            float z1 = v[1][b] + xzg1;
            float z2 = v[2][b] + xzg2;
            float z3 = v[3][b] + xzg3;
            #pragma unroll
            for (int kc2 = 0; kc2 < 4; kc2++) {
                if (kc2 == b) continue;
                float4 q = zp[(kc2 * 2 + b) * 128 + j];
                z0 += q.x; z1 += q.y; z2 += q.z; z3 += q.w;
            }
            float ig = sigm(z0);
            float fg = sigm(z1);
            float gg = ftanh(z2);
            float og = sigm(z3);
            c_r = fg * c_r + ig * gg;
            float h = og * ftanh(c_r);

            hb[(buf ^ 1) * 256 + b * 128 + j] = h;

            if (!last_only) {
                g_y0[((size_t)(bg0 + b) * TT + t) * (2 * HH) + dir * HH + j] = h;
            } else if (s == TT - 1) {
                final_out[(size_t)(bg0 + b) * (2 * HH) + dir * HH + j] = h;
            }
        }
        __syncthreads();
    }
}

// ---------------------------------------------------------------------------
extern "C" void kernel_launch(void* const* d_in, const int* in_sizes, int n_in,
                              void* d_out, int out_size)
{
    (void)in_sizes; (void)n_in; (void)out_size;
    const float* x   = (const float*)d_in[0];
    const float* W0f = (const float*)d_in[1];
    const float* U0f = (const float*)d_in[2];
    const float* b0f = (const float*)d_in[3];
    const float* W0b = (const float*)d_in[4];
    const float* U0b = (const float*)d_in[5];
    const float* b0b = (const float*)d_in[6];
    const float* W1f = (const float*)d_in[7];
    const float* U1f = (const float*)d_in[8];
    const float* b1f = (const float*)d_in[9];
    const float* W1b = (const float*)d_in[10];
    const float* U1b = (const float*)d_in[11];
    const float* b1b = (const float*)d_in[12];
    float* out = (float*)d_out;

    cudaFuncSetAttribute(gemm_bias,
        cudaFuncAttributeMaxDynamicSharedMemorySize, GEMM_SMEM_B);
    cudaFuncSetAttribute(lstm_rec,
        cudaFuncAttributeMaxDynamicSharedMemorySize, REC_SMEM_B);

    dim3 gg(8, 512);   // 512/64 n-tiles x 65536/128 m-tiles

    // Layer 0
    permU<<<512, 256>>>(U0f, U0b, 0);
    gemm_bias<<<gg, 256, GEMM_SMEM_B>>>(x, 0, W0f, b0f, 0);
    gemm_bias<<<gg, 256, GEMM_SMEM_B>>>(x, 0, W0b, b0b, 1);
    lstm_rec<<<128, 512, REC_SMEM_B>>>(0, nullptr, 0);

    // Layer 1 (input = g_y0)
    permU<<<512, 256>>>(U1f, U1b, 1);
    gemm_bias<<<gg, 256, GEMM_SMEM_B>>>(nullptr, 1, W1f, b1f, 0);
    gemm_bias<<<gg, 256, GEMM_SMEM_B>>>(nullptr, 1, W1b, b1b, 1);
    lstm_rec<<<128, 512, REC_SMEM_B>>>(1, out, 1);
}

// round 9
// speedup vs baseline: 4.7198x; 1.0148x over previous
#include <cuda_runtime.h>
#include <math.h>

typedef unsigned long long ull;

#define BB 128
#define TT 512
#define FF 256
#define HH 128
#define G4 512   // 4*H

// ---- device scratch (no allocation allowed) ----
__device__ float g_xzf[BB * TT * G4];       // input projection, forward dir
__device__ float g_xzb[BB * TT * G4];       // input projection, backward dir
__device__ float g_y0 [BB * TT * 2 * HH];   // layer-0 bidirectional output
__device__ float g_Up0[2 * 4 * HH * HH];    // permuted U layer0: [dir][g][j][k]
__device__ float g_Up1[2 * 4 * HH * HH];    // permuted U layer1

// ---- packed f32x2 helpers (Blackwell) ----
__device__ __forceinline__ float2 upk(ull v) {
    float2 r; asm("mov.b64 {%0,%1}, %2;" : "=f"(r.x), "=f"(r.y) : "l"(v)); return r;
}
__device__ __forceinline__ void fma2(ull& d, ull a, ull b) {
    asm("fma.rn.f32x2 %0, %1, %2, %0;" : "+l"(d) : "l"(a), "l"(b));
}

// ---- FFMA-only transcendentals (no MUFU) ----
__device__ __forceinline__ float fexp(float x) {
    const float L2E = 1.442695041f;
    float t = fmaf(x, L2E, 12582912.0f);       // magic round-to-nearest
    int  ti = __float_as_int(t);
    float n = t - 12582912.0f;                 // n = round(x*log2e)
    float f = fmaf(x, L2E, -n);                // f in [-0.5, 0.5]
    float p =          1.3335591e-3f;          // 2^f poly (deg 5)
    p = fmaf(p, f, 9.6181291e-3f);
    p = fmaf(p, f, 5.5504109e-2f);
    p = fmaf(p, f, 2.4022651e-1f);
    p = fmaf(p, f, 6.9314718e-1f);
    p = fmaf(p, f, 1.0f);
    int e = ((ti & 0x7FFFFF) - 0x400000) << 23;  // n as exponent bits
    return __int_as_float(__float_as_int(p) + e);
}
__device__ __forceinline__ float frcp(float d) {
    float r = __int_as_float(0x7EF477D5 - __float_as_int(d));
    r = r * fmaf(-d, r, 2.0f);
    r = r * fmaf(-d, r, 2.0f);
    r = r * fmaf(-d, r, 2.0f);
    return r;
}
__device__ __forceinline__ float sigm(float z) {
    z = fmaxf(fminf(z, 30.f), -30.f);
    return frcp(1.0f + fexp(-z));
}
__device__ __forceinline__ float ftanh(float x) {
    x = fmaxf(fminf(x, 15.f), -15.f);
    float e = fexp(-2.0f * x);
    return (1.0f - e) * frcp(1.0f + e);
}

// ---------------------------------------------------------------------------
// Permute U: dst[dir][g][j][k] = U_dir[k][g*128 + j]   (k-minor)
// ---------------------------------------------------------------------------
__global__ void permU(const float* __restrict__ Uf, const float* __restrict__ Ub,
                      int which)
{
    float* dst = which ? g_Up1 : g_Up0;
    int idx = blockIdx.x * 256 + threadIdx.x;   // [0, 131072)
    if (idx >= 2 * 4 * HH * HH) return;
    int dir = idx >> 16;
    int col = (idx >> 7) & 511;   // g*128 + j
    int k   = idx & 127;
    int g   = col >> 7;
    int j   = col & 127;
    const float* U = dir ? Ub : Uf;
    dst[idx] = U[k * G4 + g * HH + j];
}

// ---------------------------------------------------------------------------
// Projection GEMM (unchanged from R8): C[65536,512] = A[65536,256] @ W + bias
// ---------------------------------------------------------------------------
#define GEMM_SMEM_F (2 * 128 * 32 + 2 * 64 * 34)     // 12544 floats
#define GEMM_SMEM_B (GEMM_SMEM_F * 4)                // 50176 bytes

__global__ __launch_bounds__(256, 2) void gemm_bias(
    const float* __restrict__ Aext, int useY0,
    const float* __restrict__ W, const float* __restrict__ bias,
    int dstB)
{
    extern __shared__ __align__(16) float gsm[];
    float (*As)[128][32] = (float(*)[128][32])gsm;
    float (*Bs)[64][34]  = (float(*)[64][34])(gsm + 2 * 128 * 32);

    const float* A = useY0 ? g_y0 : Aext;
    float* C = dstB ? g_xzb : g_xzf;

    const int tid = threadIdx.x;
    const int tx = tid & 15;      // n-group
    const int ty = tid >> 4;      // m-group
    const int bm = blockIdx.y * 128;
    const int bn = blockIdx.x * 64;

    ull acc[8][4];
    #pragma unroll
    for (int i = 0; i < 8; i++)
        #pragma unroll
        for (int j = 0; j < 4; j++) acc[i][j] = 0ULL;

    float4 ar[4], br[2];

    {
        #pragma unroll
        for (int ii = 0; ii < 4; ii++) {
            int idx = tid + ii * 256;
            ar[ii] = *(const float4*)&A[(size_t)(bm + (idx >> 3)) * FF + (idx & 7) * 4];
        }
        #pragma unroll
        for (int ii = 0; ii < 2; ii++) {
            int idx = tid + ii * 256;
            br[ii] = *(const float4*)&W[(size_t)(idx >> 4) * G4 + bn + (idx & 15) * 4];
        }
    }
    #pragma unroll
    for (int ii = 0; ii < 4; ii++) {
        int idx = tid + ii * 256;
        *(float4*)&As[0][idx >> 3][(idx & 7) * 4] = ar[ii];
    }
    #pragma unroll
    for (int ii = 0; ii < 2; ii++) {
        int idx = tid + ii * 256;
        int kr = idx >> 4, nc = (idx & 15) * 4;
        Bs[0][nc + 0][kr] = br[ii].x;
        Bs[0][nc + 1][kr] = br[ii].y;
        Bs[0][nc + 2][kr] = br[ii].z;
        Bs[0][nc + 3][kr] = br[ii].w;
    }
    __syncthreads();

    int stage = 0;
    for (int kt = 0; kt < 8; kt++) {
        if (kt < 7) {
            const int k0 = (kt + 1) * 32;
            #pragma unroll
            for (int ii = 0; ii < 4; ii++) {
                int idx = tid + ii * 256;
                ar[ii] = *(const float4*)&A[(size_t)(bm + (idx >> 3)) * FF + k0 + (idx & 7) * 4];
            }
            #pragma unroll
            for (int ii = 0; ii < 2; ii++) {
                int idx = tid + ii * 256;
                br[ii] = *(const float4*)&W[(size_t)(k0 + (idx >> 4)) * G4 + bn + (idx & 15) * 4];
            }
        }

        #pragma unroll
        for (int kp = 0; kp < 16; kp++) {
            ull av[8], bv[4];
            #pragma unroll
            for (int i = 0; i < 8; i++)
                av[i] = *(const ull*)&As[stage][ty * 8 + i][kp * 2];
            #pragma unroll
            for (int j = 0; j < 4; j++)
                bv[j] = *(const ull*)&Bs[stage][tx + 16 * j][kp * 2];
            #pragma unroll
            for (int i = 0; i < 8; i++)
                #pragma unroll
                for (int j = 0; j < 4; j++)
                    fma2(acc[i][j], av[i], bv[j]);
        }

        if (kt < 7) {
            const int st = stage ^ 1;
            #pragma unroll
            for (int ii = 0; ii < 4; ii++) {
                int idx = tid + ii * 256;
                *(float4*)&As[st][idx >> 3][(idx & 7) * 4] = ar[ii];
            }
            #pragma unroll
            for (int ii = 0; ii < 2; ii++) {
                int idx = tid + ii * 256;
                int kr = idx >> 4, nc = (idx & 15) * 4;
                Bs[st][nc + 0][kr] = br[ii].x;
                Bs[st][nc + 1][kr] = br[ii].y;
                Bs[st][nc + 2][kr] = br[ii].z;
                Bs[st][nc + 3][kr] = br[ii].w;
            }
        }
        __syncthreads();
        stage ^= 1;
    }

    float bvx[4];
    #pragma unroll
    for (int j = 0; j < 4; j++) bvx[j] = bias[bn + tx + 16 * j];

    #pragma unroll
    for (int i = 0; i < 8; i++) {
        size_t row = (size_t)(bm + ty * 8 + i) * G4 + bn + tx;
        #pragma unroll
        for (int j = 0; j < 4; j++) {
            float2 p = upk(acc[i][j]);
            C[row + 16 * j] = p.x + p.y + bvx[j];
        }
    }
}

// ---------------------------------------------------------------------------
// Recurrence R9: 128 CTAs = (2 dirs) x (64 groups of 2 batch rows), 512 thr.
// NEW thread map: lane = kc*8 + jo  (kc = lane>>3 in 0..3, jo = lane&7),
//                 j = warp*8 + jo. All 4 kc partials of a unit live in one
//                 warp -> kc-reduction via 2 shfl.bfly rounds, ONE barrier
//                 per step (zp buffer and 2nd barrier deleted).
// U: COLPAD=100 -> every (g,j,quad) 16B-aligned -> LDS.128 (24/thread/step,
//    was 48 LDS.64). Phase banks: jo*100 mod 32 = 4*jo -> conflict-free.
// h: padded chunk stride 36 words -> kc-varying intra-warp reads stay
//    conflict-free; per-phase single-address (kc per phase) -> cheap.
// Last 8 k of each chunk in registers (ureg). Owners (kc<2) do gates for
// batch row b=kc; c state in a register. Gates FFMA-only.
// ---------------------------------------------------------------------------
#define USM_COLPAD 100
#define USM_FLOATS (512 * USM_COLPAD)              // 51200 floats
#define SM_HB_OFF  USM_FLOATS                      // hb: [2][2][144] = 576 floats
#define REC_SMEM_B ((USM_FLOATS + 576) * 4)        // 207104 bytes

__global__ __launch_bounds__(512, 1) void lstm_rec(
    int layer, float* __restrict__ final_out, int last_only)
{
    extern __shared__ __align__(16) float sm[];
    float* Usm = sm;
    float* hb  = sm + SM_HB_OFF;     // [(buf)*288 + b*144 + kc*36 + kk]

    const int tid  = threadIdx.x;
    const int w    = tid >> 5;
    const int lane = tid & 31;
    const int kc   = lane >> 3;      // 0..3  k-chunk
    const int jo   = lane & 7;
    const int j    = w * 8 + jo;     // hidden unit
    const int dir   = blockIdx.x >> 6;
    const int chunk = blockIdx.x & 63;
    const int bg0   = chunk * 2;

    const float* xz = dir ? g_xzb : g_xzf;
    const float* Up = (layer ? g_Up1 : g_Up0) + dir * 65536;

    // preload parked U (first 24 k of each chunk), COLPAD 100
    for (int idx = tid; idx < 512 * 96; idx += 512) {
        int col = idx / 96;
        int p   = idx - col * 96;
        int cc  = p / 24;
        int kk  = p - cc * 24;
        Usm[col * USM_COLPAD + p] = Up[col * 128 + cc * 32 + kk];
    }
    // register-resident U: last 8 k of this thread's chunk, 4 gates
    ull ureg[4][4];
    #pragma unroll
    for (int g = 0; g < 4; g++)
        #pragma unroll
        for (int q = 0; q < 4; q++)
            ureg[g][q] = *(const ull*)&Up[(g * 128 + j) * 128 + kc * 32 + 24 + 2 * q];

    for (int i = tid; i < 576; i += 512) hb[i] = 0.f;
    float c_r = 0.f;
    __syncthreads();

    const int hpad = kc * 36;                 // padded chunk base in hb rows
    const int jmap = (j & 31) + (j >> 5) * 36; // h store position

    for (int s = 0; s < TT; s++) {
        const int t = dir ? (TT - 1 - s) : s;
        const int buf = s & 1;

        // prefetch xz (owner lanes only; independent of h)
        float xg0 = 0.f, xg1 = 0.f, xg2 = 0.f, xg3 = 0.f;
        if (kc < 2) {
            const float* zr = xz + ((size_t)(bg0 + kc) * TT + t) * G4 + j;
            xg0 = zr[0]; xg1 = zr[HH]; xg2 = zr[2 * HH]; xg3 = zr[3 * HH];
        }

        ull acc[4][2];
        #pragma unroll
        for (int g = 0; g < 4; g++) { acc[g][0] = 0ULL; acc[g][1] = 0ULL; }

        const float* hbB = hb + buf * 288;

        // parked part: 24 k = 6 quads, LDS.128 U loads
        #pragma unroll
        for (int qq = 0; qq < 6; qq++) {
            ulonglong2 ha = *(const ulonglong2*)&hbB[hpad + qq * 4];        // b=0
            ulonglong2 hc = *(const ulonglong2*)&hbB[144 + hpad + qq * 4];  // b=1
            #pragma unroll
            for (int g = 0; g < 4; g++) {
                ulonglong2 u = *(const ulonglong2*)
                    &Usm[(g * 128 + j) * USM_COLPAD + kc * 24 + qq * 4];
                fma2(acc[g][0], ha.x, u.x); fma2(acc[g][0], ha.y, u.y);
                fma2(acc[g][1], hc.x, u.x); fma2(acc[g][1], hc.y, u.y);
            }
        }
        // register part: last 8 k = 2 quads
        #pragma unroll
        for (int qq = 0; qq < 2; qq++) {
            ulonglong2 ha = *(const ulonglong2*)&hbB[hpad + 24 + qq * 4];
            ulonglong2 hc = *(const ulonglong2*)&hbB[144 + hpad + 24 + qq * 4];
            #pragma unroll
            for (int g = 0; g < 4; g++) {
                fma2(acc[g][0], ha.x, ureg[g][2 * qq]); fma2(acc[g][0], ha.y, ureg[g][2 * qq + 1]);
                fma2(acc[g][1], hc.x, ureg[g][2 * qq]); fma2(acc[g][1], hc.y, ureg[g][2 * qq + 1]);
            }
        }

        // fold halves: v[g] = b0 partial, v[4+g] = b1 partial
        float v[8];
        #pragma unroll
        for (int g = 0; g < 4; g++) {
            float2 p0 = upk(acc[g][0]); v[g]     = p0.x + p0.y;
            float2 p1 = upk(acc[g][1]); v[4 + g] = p1.x + p1.y;
        }
        // reduce over kc (lane bits 3-4): bfly 8, 16
        #pragma unroll
        for (int q = 0; q < 8; q++) v[q] += __shfl_xor_sync(0xffffffffu, v[q], 8);
        #pragma unroll
        for (int q = 0; q < 8; q++) v[q] += __shfl_xor_sync(0xffffffffu, v[q], 16);

        if (kc < 2) {
            const int b = kc;
            float z0 = v[b * 4 + 0] + xg0;
            float z1 = v[b * 4 + 1] + xg1;
            float z2 = v[b * 4 + 2] + xg2;
            float z3 = v[b * 4 + 3] + xg3;
            float ig = sigm(z0);
            float fg = sigm(z1);
            float gg = ftanh(z2);
            float og = sigm(z3);
            c_r = fg * c_r + ig * gg;
            float h = og * ftanh(c_r);

            hb[(buf ^ 1) * 288 + b * 144 + jmap] = h;

            if (!last_only) {
                g_y0[((size_t)(bg0 + b) * TT + t) * (2 * HH) + dir * HH + j] = h;
            } else if (s == TT - 1) {
                final_out[(size_t)(bg0 + b) * (2 * HH) + dir * HH + j] = h;
            }
        }
        __syncthreads();
    }
}

// ---------------------------------------------------------------------------
extern "C" void kernel_launch(void* const* d_in, const int* in_sizes, int n_in,
                              void* d_out, int out_size)
{
    (void)in_sizes; (void)n_in; (void)out_size;
    const float* x   = (const float*)d_in[0];
    const float* W0f = (const float*)d_in[1];
    const float* U0f = (const float*)d_in[2];
    const float* b0f = (const float*)d_in[3];
    const float* W0b = (const float*)d_in[4];
    const float* U0b = (const float*)d_in[5];
    const float* b0b = (const float*)d_in[6];
    const float* W1f = (const float*)d_in[7];
    const float* U1f = (const float*)d_in[8];
    const float* b1f = (const float*)d_in[9];
    const float* W1b = (const float*)d_in[10];
    const float* U1b = (const float*)d_in[11];
    const float* b1b = (const float*)d_in[12];
    float* out = (float*)d_out;

    cudaFuncSetAttribute(gemm_bias,
        cudaFuncAttributeMaxDynamicSharedMemorySize, GEMM_SMEM_B);
    cudaFuncSetAttribute(lstm_rec,
        cudaFuncAttributeMaxDynamicSharedMemorySize, REC_SMEM_B);

    dim3 gg(8, 512);   // 512/64 n-tiles x 65536/128 m-tiles

    // Layer 0
    permU<<<512, 256>>>(U0f, U0b, 0);
    gemm_bias<<<gg, 256, GEMM_SMEM_B>>>(x, 0, W0f, b0f, 0);
    gemm_bias<<<gg, 256, GEMM_SMEM_B>>>(x, 0, W0b, b0b, 1);
    lstm_rec<<<128, 512, REC_SMEM_B>>>(0, nullptr, 0);

    // Layer 1 (input = g_y0)
    permU<<<512, 256>>>(U1f, U1b, 1);
    gemm_bias<<<gg, 256, GEMM_SMEM_B>>>(nullptr, 1, W1f, b1f, 0);
    gemm_bias<<<gg, 256, GEMM_SMEM_B>>>(nullptr, 1, W1b, b1b, 1);
    lstm_rec<<<128, 512, REC_SMEM_B>>>(1, out, 1);
}